// round 7
// baseline (speedup 1.0000x reference)
#include <cuda_runtime.h>
#include <cuda_fp16.h>
#include <cstdint>
#include <math.h>

#define N_NODES 131072
#define N_EDGES 2097152
#define N_GRAPHS 2048
#define IN_CH 12
#define HID 64
#define OUT_CH 4

// Scratch (device globals — no allocation allowed).
// Referenced ONLY inside device code (host-side use of __device__ symbols
// takes the host shadow address under ATS — the R2 bug).
__device__ int   g_degi[N_NODES];
__device__ float g_dinv[N_NODES];
__device__ int   g_rowstart[N_NODES];
__device__ int   g_cursor[N_NODES];
__device__ int   g_total;
__device__ int   g_csr_src[N_EDGES];                   // src only (norm factored out)
__device__ uint4 g_Ah_raw[(size_t)N_NODES * HID / 8];  // h' = h*dinv as __half [N, 64]
__device__ float g_B[(size_t)N_NODES * HID];           // layer-1 aggregation output (fp32)
__device__ float g_pool[N_GRAPHS * HID];
__device__ float g_cnt[N_GRAPHS];

__device__ __forceinline__ void red_add_v4(float* addr, float4 v) {
    asm volatile("red.global.add.v4.f32 [%0], {%1,%2,%3,%4};"
                 :: "l"(addr), "f"(v.x), "f"(v.y), "f"(v.z), "f"(v.w)
                 : "memory");
}

__device__ __forceinline__ unsigned int pack_half2(float a, float b) {
    __half2 h = __floats2half2_rn(a, b);
    return *(unsigned int*)&h;
}

__device__ __forceinline__ void acc_row(float4& acc, const __half* h, int s, int c) {
    uint2 u = __ldg((const uint2*)(h + (size_t)s * HID + c));
    float2 lo = __half22float2(*(__half2*)&u.x);
    float2 hi = __half22float2(*(__half2*)&u.y);
    acc.x += lo.x; acc.y += lo.y; acc.z += hi.x; acc.w += hi.y;
}

// ---------------- zero deg / pool / cnt / total ----------------
__global__ void zero_kernel() {
    int i = blockIdx.x * blockDim.x + threadIdx.x;
    if (i < N_NODES) g_degi[i] = 0;
    if (i < N_GRAPHS * HID) g_pool[i] = 0.0f;
    if (i < N_GRAPHS) g_cnt[i] = 0.0f;
    if (i == 0) g_total = 0;
}

// ---------------- degree at dst (int) ----------------
__global__ void deg_kernel(const int* __restrict__ dst) {
    int e = blockIdx.x * blockDim.x + threadIdx.x;
    if (e < N_EDGES) atomicAdd(&g_degi[dst[e]], 1);
}

// ---------------- dinv + warp-aggregated unordered scan -> rowstart/cursor ----------------
__global__ void scan_kernel() {
    int i = blockIdx.x * blockDim.x + threadIdx.x;
    int lane = threadIdx.x & 31;
    int d = g_degi[i];
    g_dinv[i] = rsqrtf((float)d + 1.0f);
    int v = d;
#pragma unroll
    for (int o = 1; o < 32; o <<= 1) {
        int t = __shfl_up_sync(0xFFFFFFFFu, v, o);
        if (lane >= o) v += t;
    }
    int total = __shfl_sync(0xFFFFFFFFu, v, 31);
    int base = 0;
    if (lane == 0) base = atomicAdd(&g_total, total);
    base = __shfl_sync(0xFFFFFFFFu, base, 0);
    int start = base + v - d;
    g_rowstart[i] = start;
    g_cursor[i] = start;
}

// ---------------- fill CSR: src per edge, grouped by dst (no norm gather) -------
__global__ void fill_kernel(const int* __restrict__ src, const int* __restrict__ dst) {
    int e = blockIdx.x * blockDim.x + threadIdx.x;
    int s = src[e];
    int d = dst[e];
    int pos = atomicAdd(&g_cursor[d], 1);
    g_csr_src[pos] = s;
}

// ---------------- GEMM1: g_Ah = half((x @ W1) * dinv[row])  ----------------
__global__ void gemm1_kernel(const float* __restrict__ x, const float* __restrict__ W1) {
    __shared__ float Ws[IN_CH * HID];   // 768
    __shared__ float Xs[64 * IN_CH];    // 768
    int tid = threadIdx.x;
    for (int i = tid; i < IN_CH * HID; i += 256) Ws[i] = W1[i];
    const float* xb = x + (size_t)blockIdx.x * 64 * IN_CH;
    for (int i = tid; i < 64 * IN_CH; i += 256) Xs[i] = xb[i];
    __syncthreads();
    int row = tid >> 2;
    int cb  = (tid & 3) << 4;
    int grow = blockIdx.x * 64 + row;
    float acc[16];
#pragma unroll
    for (int j = 0; j < 16; j++) acc[j] = 0.0f;
#pragma unroll
    for (int k = 0; k < IN_CH; k++) {
        float xv = Xs[row * IN_CH + k];
#pragma unroll
        for (int j = 0; j < 16; j++) acc[j] = fmaf(xv, Ws[k * HID + cb + j], acc[j]);
    }
    float di = g_dinv[grow];
    __half* Ah = (__half*)g_Ah_raw;
    unsigned int p[8];
#pragma unroll
    for (int j = 0; j < 8; j++) p[j] = pack_half2(acc[2 * j] * di, acc[2 * j + 1] * di);
    uint4* o = (uint4*)(Ah + (size_t)grow * HID + cb);
    o[0] = make_uint4(p[0], p[1], p[2], p[3]);
    o[1] = make_uint4(p[4], p[5], p[6], p[7]);
}

// ---------------- aggregation: warp per node, CSR gather of pre-scaled halves ---
// out = dinv[node] * (sum_edges h'[src] + h'[node]) + bias
// MODE 0: store to g_B (layer 1)
// MODE 1: relu + red into g_pool[batch[node]] (layer 2, fused pool)
template <int MODE>
__global__ void agg_kernel(const float* __restrict__ bias, const int* __restrict__ batch) {
    const __half* h = (const __half*)g_Ah_raw;
    int node = blockIdx.x * 8 + (threadIdx.x >> 5);
    int lane = threadIdx.x & 31;
    int c   = (lane & 15) << 2;  // column base (4 halves per lane)
    int hid = lane >> 4;         // which edge of the pair
    int beg = g_rowstart[node];
    int end = beg + g_degi[node];
    float4 acc  = make_float4(0.f, 0.f, 0.f, 0.f);
    float4 acc2 = make_float4(0.f, 0.f, 0.f, 0.f);
    if (hid == 0) acc_row(acc, h, node, c);   // self term (h'[node])
    int e = beg + hid;
    // unroll x2: two independent gathers in flight per half-warp
    for (; e + 2 < end; e += 4) {
        int s0 = __ldg(g_csr_src + e);
        int s1 = __ldg(g_csr_src + e + 2);
        acc_row(acc,  h, s0, c);
        acc_row(acc2, h, s1, c);
    }
    for (; e < end; e += 2) {
        int s0 = __ldg(g_csr_src + e);
        acc_row(acc, h, s0, c);
    }
    acc.x += acc2.x; acc.y += acc2.y; acc.z += acc2.z; acc.w += acc2.w;
    acc.x += __shfl_down_sync(0xFFFFFFFFu, acc.x, 16);
    acc.y += __shfl_down_sync(0xFFFFFFFFu, acc.y, 16);
    acc.z += __shfl_down_sync(0xFFFFFFFFu, acc.z, 16);
    acc.w += __shfl_down_sync(0xFFFFFFFFu, acc.w, 16);
    if (hid == 0) {
        float di = g_dinv[node];
        float4 b = *(const float4*)(bias + c);
        acc.x = fmaf(acc.x, di, b.x);
        acc.y = fmaf(acc.y, di, b.y);
        acc.z = fmaf(acc.z, di, b.z);
        acc.w = fmaf(acc.w, di, b.w);
        if (MODE == 0) {
            *(float4*)(g_B + (size_t)node * HID + c) = acc;
        } else {
            acc.x = fmaxf(acc.x, 0.f); acc.y = fmaxf(acc.y, 0.f);
            acc.z = fmaxf(acc.z, 0.f); acc.w = fmaxf(acc.w, 0.f);
            int g = __ldg(batch + node);
            red_add_v4(g_pool + g * HID + c, acc);
        }
    }
}

// ---------------- GEMM2: g_Ah = half((relu(g_B) @ W2) * dinv[row]) --------------
__global__ void gemm2_kernel(const float* __restrict__ W2) {
    __shared__ float Ws[HID * HID];
    __shared__ float rows[64 * 68];
    int tid = threadIdx.x;
    for (int i = tid; i < HID * HID; i += 256) Ws[i] = W2[i];
    int rbase = blockIdx.x * 64;
    for (int i = tid * 4; i < 64 * 64; i += 256 * 4) {
        int r = i >> 6, cc = i & 63;
        float4 v = *(const float4*)(g_B + (size_t)(rbase + r) * HID + cc);
        v.x = fmaxf(v.x, 0.0f); v.y = fmaxf(v.y, 0.0f);
        v.z = fmaxf(v.z, 0.0f); v.w = fmaxf(v.w, 0.0f);
        *(float4*)(rows + r * 68 + cc) = v;
    }
    __syncthreads();
    int r = tid >> 2;
    int cb = (tid & 3) << 4;
    float acc[16];
#pragma unroll
    for (int j = 0; j < 16; j++) acc[j] = 0.0f;
#pragma unroll
    for (int k = 0; k < HID; k++) {
        float xv = rows[r * 68 + k];
        const float4* w = (const float4*)&Ws[k * HID + cb];
#pragma unroll
        for (int q = 0; q < 4; q++) {
            float4 wv = w[q];
            acc[4 * q + 0] = fmaf(xv, wv.x, acc[4 * q + 0]);
            acc[4 * q + 1] = fmaf(xv, wv.y, acc[4 * q + 1]);
            acc[4 * q + 2] = fmaf(xv, wv.z, acc[4 * q + 2]);
            acc[4 * q + 3] = fmaf(xv, wv.w, acc[4 * q + 3]);
        }
    }
    float di = g_dinv[rbase + r];
    __half* Ah = (__half*)g_Ah_raw;
    unsigned int p[8];
#pragma unroll
    for (int j = 0; j < 8; j++) p[j] = pack_half2(acc[2 * j] * di, acc[2 * j + 1] * di);
    uint4* o = (uint4*)(Ah + (size_t)(rbase + r) * HID + cb);
    o[0] = make_uint4(p[0], p[1], p[2], p[3]);
    o[1] = make_uint4(p[4], p[5], p[6], p[7]);
}

// ---------------- graph counts (warp-aggregated; batch is sorted) ----------------
__global__ void cnt_kernel(const int* __restrict__ batch) {
    int i = blockIdx.x * blockDim.x + threadIdx.x;
    int g = batch[i];
    unsigned mask = __match_any_sync(0xFFFFFFFFu, g);
    int leader = __ffs(mask) - 1;
    if ((threadIdx.x & 31) == leader)
        atomicAdd(&g_cnt[g], (float)__popc(mask));
}

// ---------------- head: out = sigmoid((pool/cnt) @ Wfc + bfc) ----------------
__global__ void head_kernel(const float* __restrict__ Wfc, const float* __restrict__ bfc,
                            float* __restrict__ out) {
    __shared__ float Wf[HID * OUT_CH];
    if (threadIdx.x < HID * OUT_CH) Wf[threadIdx.x] = Wfc[threadIdx.x];
    __syncthreads();
    int gt = blockIdx.x * blockDim.x + threadIdx.x;
    int g = gt >> 2;
    int o = gt & 3;
    float cnt = fmaxf(g_cnt[g], 1.0f);
    float inv = 1.0f / cnt;
    float s = 0.0f;
#pragma unroll
    for (int k = 0; k < HID; k++) s = fmaf(g_pool[g * HID + k], Wf[k * OUT_CH + o], s);
    s = fmaf(s, inv, bfc[o]);
    out[gt] = 1.0f / (1.0f + expf(-s));
}

extern "C" void kernel_launch(void* const* d_in, const int* in_sizes, int n_in,
                              void* d_out, int out_size) {
    const float* x   = (const float*)d_in[0];
    const int*   ei  = (const int*)d_in[1];
    const int*   bat = (const int*)d_in[2];
    const float* W1  = (const float*)d_in[3];
    const float* b1  = (const float*)d_in[4];
    const float* W2  = (const float*)d_in[5];
    const float* b2  = (const float*)d_in[6];
    const float* Wfc = (const float*)d_in[7];
    const float* bfc = (const float*)d_in[8];
    float* out = (float*)d_out;

    const int* src = ei;
    const int* dst = ei + N_EDGES;
    const int B = 256;

    zero_kernel<<<(N_NODES + B - 1) / B, B>>>();
    deg_kernel<<<N_EDGES / B, B>>>(dst);
    scan_kernel<<<N_NODES / B, B>>>();
    fill_kernel<<<N_EDGES / B, B>>>(src, dst);

    // layer 1: gemm1 (pre-scaled half output) -> CSR gather-aggregate
    gemm1_kernel<<<N_NODES / 64, B>>>(x, W1);
    agg_kernel<0><<<N_NODES / 8, B>>>(b1, bat);

    // layer 2: gemm2 (ReLU on load, pre-scaled half output) -> agg fused with pool
    gemm2_kernel<<<N_NODES / 64, B>>>(W2);
    agg_kernel<1><<<N_NODES / 8, B>>>(b2, bat);

    cnt_kernel<<<N_NODES / B, B>>>(bat);
    head_kernel<<<(N_GRAPHS * OUT_CH) / B, B>>>(Wfc, bfc, out);
}

// round 8
// speedup vs baseline: 1.0207x; 1.0207x over previous
#include <cuda_runtime.h>
#include <cuda_fp16.h>
#include <cstdint>
#include <math.h>

#define N_NODES 131072
#define N_EDGES 2097152
#define N_GRAPHS 2048
#define IN_CH 12
#define HID 64
#define OUT_CH 4

// Scratch (device globals — no allocation allowed).
// Referenced ONLY inside device code (host-side use of __device__ symbols
// takes the host shadow address under ATS — the R2 bug).
__device__ int   g_degi[N_NODES];
__device__ float g_dinv[N_NODES];
__device__ int   g_rowstart[N_NODES];
__device__ int   g_cursor[N_NODES];
__device__ int   g_total;
__device__ int   g_csr_src[N_EDGES];                   // src only (norm factored out)
__device__ uint4 g_Ah_raw[(size_t)N_NODES * HID / 8];  // h' = h*dinv as __half [N, 64]
__device__ float g_B[(size_t)N_NODES * HID];           // layer-1 aggregation output (fp32)
__device__ float g_pool[N_GRAPHS * HID];
__device__ float g_cnt[N_GRAPHS];

__device__ __forceinline__ void red_add_v4(float* addr, float4 v) {
    asm volatile("red.global.add.v4.f32 [%0], {%1,%2,%3,%4};"
                 :: "l"(addr), "f"(v.x), "f"(v.y), "f"(v.z), "f"(v.w)
                 : "memory");
}

__device__ __forceinline__ unsigned int pack_half2(float a, float b) {
    __half2 h = __floats2half2_rn(a, b);
    return *(unsigned int*)&h;
}

// accumulate one uint4 (8 halves) into acc[8]
__device__ __forceinline__ void acc_row8(float* acc, uint4 u) {
    float2 f0 = __half22float2(*(__half2*)&u.x);
    float2 f1 = __half22float2(*(__half2*)&u.y);
    float2 f2 = __half22float2(*(__half2*)&u.z);
    float2 f3 = __half22float2(*(__half2*)&u.w);
    acc[0] += f0.x; acc[1] += f0.y; acc[2] += f1.x; acc[3] += f1.y;
    acc[4] += f2.x; acc[5] += f2.y; acc[6] += f3.x; acc[7] += f3.y;
}

// ---------------- zero deg / pool / cnt / total ----------------
__global__ void zero_kernel() {
    int i = blockIdx.x * blockDim.x + threadIdx.x;
    if (i < N_NODES) g_degi[i] = 0;
    if (i < N_GRAPHS * HID) g_pool[i] = 0.0f;
    if (i < N_GRAPHS) g_cnt[i] = 0.0f;
    if (i == 0) g_total = 0;
}

// ---------------- degree at dst (int) ----------------
__global__ void deg_kernel(const int* __restrict__ dst) {
    int e = blockIdx.x * blockDim.x + threadIdx.x;
    if (e < N_EDGES) atomicAdd(&g_degi[dst[e]], 1);
}

// ---------------- dinv + warp-aggregated unordered scan -> rowstart/cursor ----------------
__global__ void scan_kernel() {
    int i = blockIdx.x * blockDim.x + threadIdx.x;
    int lane = threadIdx.x & 31;
    int d = g_degi[i];
    g_dinv[i] = rsqrtf((float)d + 1.0f);
    int v = d;
#pragma unroll
    for (int o = 1; o < 32; o <<= 1) {
        int t = __shfl_up_sync(0xFFFFFFFFu, v, o);
        if (lane >= o) v += t;
    }
    int total = __shfl_sync(0xFFFFFFFFu, v, 31);
    int base = 0;
    if (lane == 0) base = atomicAdd(&g_total, total);
    base = __shfl_sync(0xFFFFFFFFu, base, 0);
    int start = base + v - d;
    g_rowstart[i] = start;
    g_cursor[i] = start;
}

// ---------------- fill CSR: src per edge, grouped by dst (no norm gather) -------
__global__ void fill_kernel(const int* __restrict__ src, const int* __restrict__ dst) {
    int e = blockIdx.x * blockDim.x + threadIdx.x;
    int s = src[e];
    int d = dst[e];
    int pos = atomicAdd(&g_cursor[d], 1);
    g_csr_src[pos] = s;
}

// ---------------- GEMM1: g_Ah = half((x @ W1) * dinv[row])  ----------------
__global__ void gemm1_kernel(const float* __restrict__ x, const float* __restrict__ W1) {
    __shared__ float Ws[IN_CH * HID];   // 768
    __shared__ float Xs[64 * IN_CH];    // 768
    int tid = threadIdx.x;
    for (int i = tid; i < IN_CH * HID; i += 256) Ws[i] = W1[i];
    const float* xb = x + (size_t)blockIdx.x * 64 * IN_CH;
    for (int i = tid; i < 64 * IN_CH; i += 256) Xs[i] = xb[i];
    __syncthreads();
    int row = tid >> 2;
    int cb  = (tid & 3) << 4;
    int grow = blockIdx.x * 64 + row;
    float acc[16];
#pragma unroll
    for (int j = 0; j < 16; j++) acc[j] = 0.0f;
#pragma unroll
    for (int k = 0; k < IN_CH; k++) {
        float xv = Xs[row * IN_CH + k];
#pragma unroll
        for (int j = 0; j < 16; j++) acc[j] = fmaf(xv, Ws[k * HID + cb + j], acc[j]);
    }
    float di = g_dinv[grow];
    __half* Ah = (__half*)g_Ah_raw;
    unsigned int p[8];
#pragma unroll
    for (int j = 0; j < 8; j++) p[j] = pack_half2(acc[2 * j] * di, acc[2 * j + 1] * di);
    uint4* o = (uint4*)(Ah + (size_t)grow * HID + cb);
    o[0] = make_uint4(p[0], p[1], p[2], p[3]);
    o[1] = make_uint4(p[4], p[5], p[6], p[7]);
}

// ---------------- aggregation: warp per node, 8 lanes/edge, 4 edges in flight ---
// out = dinv[node] * (sum_edges h'[src] + h'[node]) + bias
// MODE 0: store to g_B (layer 1)
// MODE 1: relu + red into g_pool[batch[node]] (layer 2, fused pool)
template <int MODE>
__global__ void agg_kernel(const float* __restrict__ bias, const int* __restrict__ batch) {
    const __half* h = (const __half*)g_Ah_raw;
    int node = blockIdx.x * 8 + (threadIdx.x >> 5);
    int lane = threadIdx.x & 31;
    int grp = lane >> 3;        // 4 edge groups
    int sub = lane & 7;         // 8 lanes per edge; each loads uint4 = 8 halves
    int c   = sub << 3;         // column base
    int beg = g_rowstart[node];
    int end = beg + g_degi[node];
    float acc[8];
#pragma unroll
    for (int j = 0; j < 8; j++) acc[j] = 0.0f;
    if (grp == 0) {   // self term h'[node]
        uint4 u = __ldg((const uint4*)(h + (size_t)node * HID + c));
        acc_row8(acc, u);
    }
    for (int e = beg + grp; e < end; e += 4) {
        int s = __ldg(g_csr_src + e);
        uint4 u = __ldg((const uint4*)(h + (size_t)s * HID + c));
        acc_row8(acc, u);
    }
    // reduce 4 groups -> group 0
#pragma unroll
    for (int j = 0; j < 8; j++) {
        acc[j] += __shfl_down_sync(0xFFFFFFFFu, acc[j], 16);
        acc[j] += __shfl_down_sync(0xFFFFFFFFu, acc[j], 8);
    }
    if (grp == 0) {
        float di = g_dinv[node];
        float4 b0 = *(const float4*)(bias + c);
        float4 b1 = *(const float4*)(bias + c + 4);
        float4 r0, r1;
        r0.x = fmaf(acc[0], di, b0.x); r0.y = fmaf(acc[1], di, b0.y);
        r0.z = fmaf(acc[2], di, b0.z); r0.w = fmaf(acc[3], di, b0.w);
        r1.x = fmaf(acc[4], di, b1.x); r1.y = fmaf(acc[5], di, b1.y);
        r1.z = fmaf(acc[6], di, b1.z); r1.w = fmaf(acc[7], di, b1.w);
        if (MODE == 0) {
            float* o = g_B + (size_t)node * HID + c;
            *(float4*)o = r0;
            *(float4*)(o + 4) = r1;
        } else {
            r0.x = fmaxf(r0.x, 0.f); r0.y = fmaxf(r0.y, 0.f);
            r0.z = fmaxf(r0.z, 0.f); r0.w = fmaxf(r0.w, 0.f);
            r1.x = fmaxf(r1.x, 0.f); r1.y = fmaxf(r1.y, 0.f);
            r1.z = fmaxf(r1.z, 0.f); r1.w = fmaxf(r1.w, 0.f);
            int g = __ldg(batch + node);
            red_add_v4(g_pool + g * HID + c, r0);
            red_add_v4(g_pool + g * HID + c + 4, r1);
        }
    }
}

// ---------------- GEMM2: g_Ah = half((relu(g_B) @ W2) * dinv[row]) --------------
__global__ void gemm2_kernel(const float* __restrict__ W2) {
    __shared__ float Ws[HID * HID];
    __shared__ float rows[64 * 68];
    int tid = threadIdx.x;
    for (int i = tid; i < HID * HID; i += 256) Ws[i] = W2[i];
    int rbase = blockIdx.x * 64;
    for (int i = tid * 4; i < 64 * 64; i += 256 * 4) {
        int r = i >> 6, cc = i & 63;
        float4 v = *(const float4*)(g_B + (size_t)(rbase + r) * HID + cc);
        v.x = fmaxf(v.x, 0.0f); v.y = fmaxf(v.y, 0.0f);
        v.z = fmaxf(v.z, 0.0f); v.w = fmaxf(v.w, 0.0f);
        *(float4*)(rows + r * 68 + cc) = v;
    }
    __syncthreads();
    int r = tid >> 2;
    int cb = (tid & 3) << 4;
    float acc[16];
#pragma unroll
    for (int j = 0; j < 16; j++) acc[j] = 0.0f;
#pragma unroll
    for (int k = 0; k < HID; k++) {
        float xv = rows[r * 68 + k];
        const float4* w = (const float4*)&Ws[k * HID + cb];
#pragma unroll
        for (int q = 0; q < 4; q++) {
            float4 wv = w[q];
            acc[4 * q + 0] = fmaf(xv, wv.x, acc[4 * q + 0]);
            acc[4 * q + 1] = fmaf(xv, wv.y, acc[4 * q + 1]);
            acc[4 * q + 2] = fmaf(xv, wv.z, acc[4 * q + 2]);
            acc[4 * q + 3] = fmaf(xv, wv.w, acc[4 * q + 3]);
        }
    }
    float di = g_dinv[rbase + r];
    __half* Ah = (__half*)g_Ah_raw;
    unsigned int p[8];
#pragma unroll
    for (int j = 0; j < 8; j++) p[j] = pack_half2(acc[2 * j] * di, acc[2 * j + 1] * di);
    uint4* o = (uint4*)(Ah + (size_t)(rbase + r) * HID + cb);
    o[0] = make_uint4(p[0], p[1], p[2], p[3]);
    o[1] = make_uint4(p[4], p[5], p[6], p[7]);
}

// ---------------- graph counts (warp-aggregated; batch is sorted) ----------------
__global__ void cnt_kernel(const int* __restrict__ batch) {
    int i = blockIdx.x * blockDim.x + threadIdx.x;
    int g = batch[i];
    unsigned mask = __match_any_sync(0xFFFFFFFFu, g);
    int leader = __ffs(mask) - 1;
    if ((threadIdx.x & 31) == leader)
        atomicAdd(&g_cnt[g], (float)__popc(mask));
}

// ---------------- head: out = sigmoid((pool/cnt) @ Wfc + bfc) ----------------
__global__ void head_kernel(const float* __restrict__ Wfc, const float* __restrict__ bfc,
                            float* __restrict__ out) {
    __shared__ float Wf[HID * OUT_CH];
    if (threadIdx.x < HID * OUT_CH) Wf[threadIdx.x] = Wfc[threadIdx.x];
    __syncthreads();
    int gt = blockIdx.x * blockDim.x + threadIdx.x;
    int g = gt >> 2;
    int o = gt & 3;
    float cnt = fmaxf(g_cnt[g], 1.0f);
    float inv = 1.0f / cnt;
    float s = 0.0f;
#pragma unroll
    for (int k = 0; k < HID; k++) s = fmaf(g_pool[g * HID + k], Wf[k * OUT_CH + o], s);
    s = fmaf(s, inv, bfc[o]);
    out[gt] = 1.0f / (1.0f + expf(-s));
}

extern "C" void kernel_launch(void* const* d_in, const int* in_sizes, int n_in,
                              void* d_out, int out_size) {
    const float* x   = (const float*)d_in[0];
    const int*   ei  = (const int*)d_in[1];
    const int*   bat = (const int*)d_in[2];
    const float* W1  = (const float*)d_in[3];
    const float* b1  = (const float*)d_in[4];
    const float* W2  = (const float*)d_in[5];
    const float* b2  = (const float*)d_in[6];
    const float* Wfc = (const float*)d_in[7];
    const float* bfc = (const float*)d_in[8];
    float* out = (float*)d_out;

    const int* src = ei;
    const int* dst = ei + N_EDGES;
    const int B = 256;

    zero_kernel<<<(N_NODES + B - 1) / B, B>>>();
    deg_kernel<<<N_EDGES / B, B>>>(dst);
    scan_kernel<<<N_NODES / B, B>>>();
    fill_kernel<<<N_EDGES / B, B>>>(src, dst);

    // layer 1: gemm1 (pre-scaled half output) -> CSR gather-aggregate
    gemm1_kernel<<<N_NODES / 64, B>>>(x, W1);
    agg_kernel<0><<<N_NODES / 8, B>>>(b1, bat);

    // layer 2: gemm2 (ReLU on load, pre-scaled half output) -> agg fused with pool
    gemm2_kernel<<<N_NODES / 64, B>>>(W2);
    agg_kernel<1><<<N_NODES / 8, B>>>(b2, bat);

    cnt_kernel<<<N_NODES / B, B>>>(bat);
    head_kernel<<<(N_GRAPHS * OUT_CH) / B, B>>>(Wfc, bfc, out);
}

// round 9
// speedup vs baseline: 1.0404x; 1.0193x over previous
#include <cuda_runtime.h>
#include <cuda_fp16.h>
#include <cstdint>
#include <math.h>

#define N_NODES 131072
#define N_EDGES 2097152
#define N_GRAPHS 2048
#define IN_CH 12
#define HID 64
#define OUT_CH 4

// Scratch (device globals — no allocation allowed).
// Referenced ONLY inside device code (host-side use of __device__ symbols
// takes the host shadow address under ATS — the R2 bug).
__device__ int   g_degi[N_NODES];
__device__ float g_dinv[N_NODES];
__device__ int   g_rowstart[N_NODES];
__device__ int   g_cursor[N_NODES];
__device__ int   g_total;
__device__ int   g_csr_src[N_EDGES];                   // src only (norm factored out)
__device__ uint4 g_Ah_raw[(size_t)N_NODES * HID / 8];  // h' = h*dinv as __half [N, 64]
__device__ uint4 g_Ah2_raw[(size_t)N_NODES * HID / 8]; // layer-2 h' (separate to avoid RAW across phases)
__device__ float g_pool[N_GRAPHS * HID];
__device__ float g_cnt[N_GRAPHS];

__device__ __forceinline__ void red_add_v4(float* addr, float4 v) {
    asm volatile("red.global.add.v4.f32 [%0], {%1,%2,%3,%4};"
                 :: "l"(addr), "f"(v.x), "f"(v.y), "f"(v.z), "f"(v.w)
                 : "memory");
}

__device__ __forceinline__ unsigned int pack_half2(float a, float b) {
    __half2 h = __floats2half2_rn(a, b);
    return *(unsigned int*)&h;
}

// accumulate one uint4 (8 halves) into acc[8]
__device__ __forceinline__ void acc_row8(float* acc, uint4 u) {
    float2 f0 = __half22float2(*(__half2*)&u.x);
    float2 f1 = __half22float2(*(__half2*)&u.y);
    float2 f2 = __half22float2(*(__half2*)&u.z);
    float2 f3 = __half22float2(*(__half2*)&u.w);
    acc[0] += f0.x; acc[1] += f0.y; acc[2] += f1.x; acc[3] += f1.y;
    acc[4] += f2.x; acc[5] += f2.y; acc[6] += f3.x; acc[7] += f3.y;
}

// ---------------- zero deg / pool / cnt / total ----------------
__global__ void zero_kernel() {
    int i = blockIdx.x * blockDim.x + threadIdx.x;
    if (i < N_NODES) g_degi[i] = 0;
    if (i < N_GRAPHS * HID) g_pool[i] = 0.0f;
    if (i < N_GRAPHS) g_cnt[i] = 0.0f;
    if (i == 0) g_total = 0;
}

// ---------------- degree at dst (edges) + graph counts (nodes), one pass --------
__global__ void deg_cnt_kernel(const int* __restrict__ dst, const int* __restrict__ batch) {
    int t = blockIdx.x * blockDim.x + threadIdx.x;
    if (t < N_EDGES) atomicAdd(&g_degi[dst[t]], 1);
    if (t < N_NODES) {
        int g = batch[t];
        unsigned mask = __match_any_sync(__activemask(), g);
        int leader = __ffs(mask) - 1;
        if ((threadIdx.x & 31) == leader)
            atomicAdd(&g_cnt[g], (float)__popc(mask));
    }
}

// ---------------- dinv + warp-aggregated unordered scan -> rowstart/cursor ------
__global__ void scan_kernel() {
    int i = blockIdx.x * blockDim.x + threadIdx.x;
    int lane = threadIdx.x & 31;
    int d = g_degi[i];
    g_dinv[i] = rsqrtf((float)d + 1.0f);
    int v = d;
#pragma unroll
    for (int o = 1; o < 32; o <<= 1) {
        int t = __shfl_up_sync(0xFFFFFFFFu, v, o);
        if (lane >= o) v += t;
    }
    int total = __shfl_sync(0xFFFFFFFFu, v, 31);
    int base = 0;
    if (lane == 0) base = atomicAdd(&g_total, total);
    base = __shfl_sync(0xFFFFFFFFu, base, 0);
    int start = base + v - d;
    g_rowstart[i] = start;
    g_cursor[i] = start;
}

// ---------------- fused: fill CSR (blocks 0..8191) + GEMM1 (blocks 8192..10239) --
#define FILL_BLOCKS (N_EDGES / 256)
__global__ void fill_gemm1_kernel(const int* __restrict__ src, const int* __restrict__ dst,
                                  const float* __restrict__ x, const float* __restrict__ W1) {
    if (blockIdx.x < FILL_BLOCKS) {
        int e = blockIdx.x * 256 + threadIdx.x;
        int s = src[e];
        int d = dst[e];
        int pos = atomicAdd(&g_cursor[d], 1);
        g_csr_src[pos] = s;
        return;
    }
    // ---- GEMM1: g_Ah = half((x @ W1) * dinv[row]) ----
    __shared__ float Ws[IN_CH * HID];   // 768
    __shared__ float Xs[64 * IN_CH];    // 768
    int blk = blockIdx.x - FILL_BLOCKS;
    int tid = threadIdx.x;
    for (int i = tid; i < IN_CH * HID; i += 256) Ws[i] = W1[i];
    const float* xb = x + (size_t)blk * 64 * IN_CH;
    for (int i = tid; i < 64 * IN_CH; i += 256) Xs[i] = xb[i];
    __syncthreads();
    int row = tid >> 2;
    int cb  = (tid & 3) << 4;
    int grow = blk * 64 + row;
    float acc[16];
#pragma unroll
    for (int j = 0; j < 16; j++) acc[j] = 0.0f;
#pragma unroll
    for (int k = 0; k < IN_CH; k++) {
        float xv = Xs[row * IN_CH + k];
#pragma unroll
        for (int j = 0; j < 16; j++) acc[j] = fmaf(xv, Ws[k * HID + cb + j], acc[j]);
    }
    float di = g_dinv[grow];
    __half* Ah = (__half*)g_Ah_raw;
    unsigned int p[8];
#pragma unroll
    for (int j = 0; j < 8; j++) p[j] = pack_half2(acc[2 * j] * di, acc[2 * j + 1] * di);
    uint4* o = (uint4*)(Ah + (size_t)grow * HID + cb);
    o[0] = make_uint4(p[0], p[1], p[2], p[3]);
    o[1] = make_uint4(p[4], p[5], p[6], p[7]);
}

// ---------------- fused: agg layer1 (to smem, ReLU) + GEMM2 -> g_Ah2 ------------
// Block = 256 threads handles 64 nodes. Phase A: 8 warps x 8 nodes CSR gather,
// rows[r] = relu(dinv*sum + bias). Phase B: rows @ W2, scale by dinv, pack half.
__global__ void agg1_gemm2_kernel(const float* __restrict__ b1, const float* __restrict__ W2) {
    __shared__ float Ws[HID * HID];      // 16 KB
    __shared__ float rows[64 * 68];      // 17 KB
    const __half* h = (const __half*)g_Ah_raw;
    int tid = threadIdx.x;
    int rbase = blockIdx.x * 64;
    for (int i = tid; i < HID * HID; i += 256) Ws[i] = W2[i];

    // ---- Phase A: aggregate 64 nodes ----
    int wid = tid >> 5;
    int lane = tid & 31;
    int grp = lane >> 3;
    int sub = lane & 7;
    int c   = sub << 3;
    float4 bb0 = *(const float4*)(b1 + c);
    float4 bb1 = *(const float4*)(b1 + c + 4);
#pragma unroll
    for (int nn = 0; nn < 8; nn++) {
        int node = rbase + wid * 8 + nn;
        int beg = g_rowstart[node];
        int end = beg + g_degi[node];
        float acc[8];
#pragma unroll
        for (int j = 0; j < 8; j++) acc[j] = 0.0f;
        if (grp == 0) {
            uint4 u = __ldg((const uint4*)(h + (size_t)node * HID + c));
            acc_row8(acc, u);
        }
        for (int e = beg + grp; e < end; e += 4) {
            int s = __ldg(g_csr_src + e);
            uint4 u = __ldg((const uint4*)(h + (size_t)s * HID + c));
            acc_row8(acc, u);
        }
#pragma unroll
        for (int j = 0; j < 8; j++) {
            acc[j] += __shfl_down_sync(0xFFFFFFFFu, acc[j], 16);
            acc[j] += __shfl_down_sync(0xFFFFFFFFu, acc[j], 8);
        }
        if (grp == 0) {
            float di = g_dinv[node];
            int r = wid * 8 + nn;
            float* o = rows + r * 68 + c;
            o[0] = fmaxf(fmaf(acc[0], di, bb0.x), 0.f);
            o[1] = fmaxf(fmaf(acc[1], di, bb0.y), 0.f);
            o[2] = fmaxf(fmaf(acc[2], di, bb0.z), 0.f);
            o[3] = fmaxf(fmaf(acc[3], di, bb0.w), 0.f);
            o[4] = fmaxf(fmaf(acc[4], di, bb1.x), 0.f);
            o[5] = fmaxf(fmaf(acc[5], di, bb1.y), 0.f);
            o[6] = fmaxf(fmaf(acc[6], di, bb1.z), 0.f);
            o[7] = fmaxf(fmaf(acc[7], di, bb1.w), 0.f);
        }
    }
    __syncthreads();

    // ---- Phase B: GEMM2 ----
    int r = tid >> 2;
    int cb = (tid & 3) << 4;
    float acc[16];
#pragma unroll
    for (int j = 0; j < 16; j++) acc[j] = 0.0f;
#pragma unroll
    for (int k = 0; k < HID; k++) {
        float xv = rows[r * 68 + k];
        const float4* w = (const float4*)&Ws[k * HID + cb];
#pragma unroll
        for (int q = 0; q < 4; q++) {
            float4 wv = w[q];
            acc[4 * q + 0] = fmaf(xv, wv.x, acc[4 * q + 0]);
            acc[4 * q + 1] = fmaf(xv, wv.y, acc[4 * q + 1]);
            acc[4 * q + 2] = fmaf(xv, wv.z, acc[4 * q + 2]);
            acc[4 * q + 3] = fmaf(xv, wv.w, acc[4 * q + 3]);
        }
    }
    float di = g_dinv[rbase + r];
    __half* Ah2 = (__half*)g_Ah2_raw;
    unsigned int p[8];
#pragma unroll
    for (int j = 0; j < 8; j++) p[j] = pack_half2(acc[2 * j] * di, acc[2 * j + 1] * di);
    uint4* o = (uint4*)(Ah2 + (size_t)(rbase + r) * HID + cb);
    o[0] = make_uint4(p[0], p[1], p[2], p[3]);
    o[1] = make_uint4(p[4], p[5], p[6], p[7]);
}

// ---------------- agg layer2: warp per node + fused ReLU + pool red --------------
__global__ void agg2_kernel(const float* __restrict__ b2, const int* __restrict__ batch) {
    const __half* h = (const __half*)g_Ah2_raw;
    int node = blockIdx.x * 8 + (threadIdx.x >> 5);
    int lane = threadIdx.x & 31;
    int grp = lane >> 3;
    int sub = lane & 7;
    int c   = sub << 3;
    int beg = g_rowstart[node];
    int end = beg + g_degi[node];
    float acc[8];
#pragma unroll
    for (int j = 0; j < 8; j++) acc[j] = 0.0f;
    if (grp == 0) {
        uint4 u = __ldg((const uint4*)(h + (size_t)node * HID + c));
        acc_row8(acc, u);
    }
    for (int e = beg + grp; e < end; e += 4) {
        int s = __ldg(g_csr_src + e);
        uint4 u = __ldg((const uint4*)(h + (size_t)s * HID + c));
        acc_row8(acc, u);
    }
#pragma unroll
    for (int j = 0; j < 8; j++) {
        acc[j] += __shfl_down_sync(0xFFFFFFFFu, acc[j], 16);
        acc[j] += __shfl_down_sync(0xFFFFFFFFu, acc[j], 8);
    }
    if (grp == 0) {
        float di = g_dinv[node];
        float4 b0 = *(const float4*)(b2 + c);
        float4 b1 = *(const float4*)(b2 + c + 4);
        float4 r0, r1;
        r0.x = fmaxf(fmaf(acc[0], di, b0.x), 0.f);
        r0.y = fmaxf(fmaf(acc[1], di, b0.y), 0.f);
        r0.z = fmaxf(fmaf(acc[2], di, b0.z), 0.f);
        r0.w = fmaxf(fmaf(acc[3], di, b0.w), 0.f);
        r1.x = fmaxf(fmaf(acc[4], di, b1.x), 0.f);
        r1.y = fmaxf(fmaf(acc[5], di, b1.y), 0.f);
        r1.z = fmaxf(fmaf(acc[6], di, b1.z), 0.f);
        r1.w = fmaxf(fmaf(acc[7], di, b1.w), 0.f);
        int g = __ldg(batch + node);
        red_add_v4(g_pool + g * HID + c, r0);
        red_add_v4(g_pool + g * HID + c + 4, r1);
    }
}

// ---------------- head: out = sigmoid((pool/cnt) @ Wfc + bfc) ----------------
__global__ void head_kernel(const float* __restrict__ Wfc, const float* __restrict__ bfc,
                            float* __restrict__ out) {
    __shared__ float Wf[HID * OUT_CH];
    if (threadIdx.x < HID * OUT_CH) Wf[threadIdx.x] = Wfc[threadIdx.x];
    __syncthreads();
    int gt = blockIdx.x * blockDim.x + threadIdx.x;
    int g = gt >> 2;
    int o = gt & 3;
    float cnt = fmaxf(g_cnt[g], 1.0f);
    float inv = 1.0f / cnt;
    float s = 0.0f;
#pragma unroll
    for (int k = 0; k < HID; k++) s = fmaf(g_pool[g * HID + k], Wf[k * OUT_CH + o], s);
    s = fmaf(s, inv, bfc[o]);
    out[gt] = 1.0f / (1.0f + expf(-s));
}

extern "C" void kernel_launch(void* const* d_in, const int* in_sizes, int n_in,
                              void* d_out, int out_size) {
    const float* x   = (const float*)d_in[0];
    const int*   ei  = (const int*)d_in[1];
    const int*   bat = (const int*)d_in[2];
    const float* W1  = (const float*)d_in[3];
    const float* b1  = (const float*)d_in[4];
    const float* W2  = (const float*)d_in[5];
    const float* b2  = (const float*)d_in[6];
    const float* Wfc = (const float*)d_in[7];
    const float* bfc = (const float*)d_in[8];
    float* out = (float*)d_out;

    const int* src = ei;
    const int* dst = ei + N_EDGES;
    const int B = 256;

    zero_kernel<<<(N_NODES + B - 1) / B, B>>>();
    deg_cnt_kernel<<<N_EDGES / B, B>>>(dst, bat);
    scan_kernel<<<N_NODES / B, B>>>();
    fill_gemm1_kernel<<<FILL_BLOCKS + N_NODES / 64, B>>>(src, dst, x, W1);
    agg1_gemm2_kernel<<<N_NODES / 64, B>>>(b1, W2);
    agg2_kernel<<<N_NODES / 8, B>>>(b2, bat);
    head_kernel<<<(N_GRAPHS * OUT_CH) / B, B>>>(Wfc, bfc, out);
}